// round 8
// baseline (speedup 1.0000x reference)
#include <cuda_runtime.h>

#define NN 1024
#define DD 128

// ---------------------------------------------------------------------------
// Device scratch (allocation-free)
// ---------------------------------------------------------------------------
__device__ float g_PIB [NN * DD];                  // pi + b1, row-major (for ci)
__device__ float g_PIBT[DD * NN];                  // pi + b1, transposed [d][i]
__device__ float g_PJ  [NN * DD];                  // pj, row-major (for cj)
__device__ unsigned long long g_PJPL[DD * NN / 2]; // packed {v,v}: j%4 in {0,1}
__device__ unsigned long long g_PJPH[DD * NN / 2]; // packed {v,v}: j%4 in {2,3}
__device__ float g_W2H [DD];                       // 0.5 * W2
__device__ float g_ci  [NN];
__device__ float g_cj  [NN];

// ---------------------------------------------------------------------------
// f32x2 packed helpers (sm_103a)
// ---------------------------------------------------------------------------
__device__ __forceinline__ unsigned long long pack2(float lo, float hi) {
    unsigned long long r;
    asm("mov.b64 %0, {%1, %2};" : "=l"(r) : "f"(lo), "f"(hi));
    return r;
}
__device__ __forceinline__ void unpack2(unsigned long long v, float& lo, float& hi) {
    asm("mov.b64 {%0, %1}, %2;" : "=f"(lo), "=f"(hi) : "l"(v));
}
__device__ __forceinline__ unsigned long long add2(unsigned long long a, unsigned long long b) {
    unsigned long long r;
    asm("add.rn.f32x2 %0, %1, %2;" : "=l"(r) : "l"(a), "l"(b));
    return r;
}
__device__ __forceinline__ unsigned long long fma2(unsigned long long a, unsigned long long b,
                                                   unsigned long long c) {
    unsigned long long r;
    asm("fma.rn.f32x2 %0, %1, %2, %3;" : "=l"(r) : "l"(a), "l"(b), "l"(c));
    return r;
}
#define ABS2_MASK 0x7FFFFFFF7FFFFFFFULL

// ---------------------------------------------------------------------------
// Kernel A: prep (reverted to proven v3 structure).
// 128 blocks x 512 threads. dc = tid&255 (concat column), h = tid>>8,
// 4 rows each, scalar W1 loads unroll 16.
// pi half -> g_PIB rows + g_PIBT (float4). pj half -> g_PJ rows + packed
// broadcast pairs into g_PJPL/g_PJPH (layout: L[d][2t+s] = pack(pj[4t+s]),
// H[d][2t+s] = pack(pj[4t+2+s]) so pair's LDS.128s are contiguous).
// ---------------------------------------------------------------------------
__global__ void __launch_bounds__(512) prep_kernel(
    const float* __restrict__ z, const float* __restrict__ W1,
    const float* __restrict__ b1, const float* __restrict__ W2)
{
    __shared__ float zs[8][DD];
    const int tid = threadIdx.x;         // 0..511
    const int dc  = tid & 255;           // concat output column
    const int h   = tid >> 8;            // row half (0/1) -> rows 4h..4h+3
    const int i0  = blockIdx.x * 8;

    if (blockIdx.x == 0 && tid < DD) g_W2H[tid] = 0.5f * W2[tid];

    if (tid < 256)
        ((float4*)zs)[tid] = ((const float4*)(z + i0 * DD))[tid];
    __syncthreads();

    const bool is_pi = (dc < DD);
    const int  d     = is_pi ? dc : dc - DD;
    const float* wcol = is_pi ? (W1 + d) : (W1 + DD * DD + d);
    const int r0 = 4 * h;

    float acc[4] = {0.f, 0.f, 0.f, 0.f};

    #pragma unroll 16
    for (int k = 0; k < DD; k++) {
        const float w = __ldg(&wcol[k * DD]);
        #pragma unroll
        for (int ii = 0; ii < 4; ii++)
            acc[ii] = fmaf(zs[r0 + ii][k], w, acc[ii]);
    }

    if (is_pi) {
        const float bb = __ldg(&b1[d]);
        #pragma unroll
        for (int ii = 0; ii < 4; ii++) acc[ii] += bb;
        #pragma unroll
        for (int ii = 0; ii < 4; ii++)
            g_PIB[(i0 + r0 + ii) * DD + d] = acc[ii];     // coalesced across dc
        *(float4*)&g_PIBT[d * NN + i0 + r0] = *(float4*)&acc[0];
    } else {
        #pragma unroll
        for (int ii = 0; ii < 4; ii++)
            g_PJ[(i0 + r0 + ii) * DD + d] = acc[ii];
        const int jg = i0 + r0;              // multiple of 4
        const int q  = jg >> 1;              // even -> 16B aligned
        ulonglong2 lv, hv;
        lv.x = pack2(acc[0], acc[0]);        // j = jg
        lv.y = pack2(acc[1], acc[1]);        // j = jg+1
        hv.x = pack2(acc[2], acc[2]);        // j = jg+2
        hv.y = pack2(acc[3], acc[3]);        // j = jg+3
        *(ulonglong2*)&g_PJPL[d * (NN / 2) + q] = lv;
        *(ulonglong2*)&g_PJPH[d * (NN / 2) + q] = hv;
    }
}

// ---------------------------------------------------------------------------
// Kernel B: ci[i] = g_PIB[i,:] . g_W2H ; cj[j] = g_PJ[j,:] . g_W2H
// One warp per row: 256 blocks x 256 threads = 2048 warps = 2048 rows.
// ---------------------------------------------------------------------------
__global__ void __launch_bounds__(256) cicj_kernel()
{
    const int warp = blockIdx.x * 8 + (threadIdx.x >> 5);
    const int lane = threadIdx.x & 31;
    const bool is_ci = warp < NN;
    const int  row   = is_ci ? warp : warp - NN;
    const float* src = is_ci ? (g_PIB + row * DD) : (g_PJ + row * DD);

    float4 v = *(const float4*)(src + lane * 4);
    float4 w = *(const float4*)(g_W2H + lane * 4);
    float s = v.x * w.x + v.y * w.y + v.z * w.z + v.w * w.w;
    #pragma unroll
    for (int off = 16; off; off >>= 1)
        s += __shfl_down_sync(0xFFFFFFFFu, s, off);
    if (lane == 0) {
        if (is_ci) g_ci[row] = s; else g_cj[row] = s;
    }
}

// ---------------------------------------------------------------------------
// Kernel C (v2): q[i,j] = ci[i] + cj[j] + sum_d w'_d |pi[d,i] + pj[d,j]| + b2
// Tile 64i x 64j, 512 threads (16 warps), 1 i-pack x 4 j per thread (8 elem).
// d chunked (CH=32): smem ~25KB -> 2+ blocks/SM; 4096 total warps (27.7/SM).
// All inner LDS conflict-free; pj pre-packed {v,v} -> zero pack MOVs.
// ---------------------------------------------------------------------------
#define CH 32

__global__ void __launch_bounds__(512, 2) pair_kernel(
    const float* __restrict__ b2, float* __restrict__ out)
{
    __shared__ float               pisS[CH][64];   //  8 KB
    __shared__ unsigned long long  pjLS[CH][32];   //  8 KB
    __shared__ unsigned long long  pjHS[CH][32];   //  8 KB
    __shared__ unsigned long long  w2s[DD];        //  1 KB

    const int tid = threadIdx.x;          // 0..511
    const int tx  = tid & 15;             // -> 4 j
    const int py  = tid >> 4;             // 0..31 -> i-pack (2 i)
    const int ib  = blockIdx.y * 64;
    const int jb  = blockIdx.x * 64;

    if (tid < DD) {
        const float w = g_W2H[tid];
        w2s[tid] = pack2(w, w);
    }

    unsigned long long a0 = 0ULL, a1 = 0ULL, a2 = 0ULL, a3 = 0ULL;

    const int dr = tid >> 4;              // 0..31 (d-row for staging)
    const int q  = tid & 15;

    for (int c = 0; c < 4; c++) {
        const int d0 = c * CH;
        if (c) __syncthreads();           // previous chunk fully consumed
        // stage pi: 32 x 64 floats, one float4 per thread (coalesced)
        *(float4*)&pisS[dr][q * 4] =
            *(const float4*)&g_PIBT[(d0 + dr) * NN + ib + q * 4];
        // stage packed pj: 32 x 32 ull per array, one ull2 per thread
        *(ulonglong2*)&pjLS[dr][q * 2] =
            *(const ulonglong2*)&g_PJPL[(d0 + dr) * (NN / 2) + (jb >> 1) + q * 2];
        *(ulonglong2*)&pjHS[dr][q * 2] =
            *(const ulonglong2*)&g_PJPH[(d0 + dr) * (NN / 2) + (jb >> 1) + q * 2];
        __syncthreads();

        #pragma unroll 8
        for (int dd = 0; dd < CH; dd++) {
            const unsigned long long aA =
                *(const unsigned long long*)&pisS[dd][py * 2];
            const unsigned long long wd = w2s[d0 + dd];
            const ulonglong2 BL = *(const ulonglong2*)&pjLS[dd][tx * 2];
            const ulonglong2 BH = *(const ulonglong2*)&pjHS[dd][tx * 2];

            unsigned long long t;
            t = add2(aA, BL.x) & ABS2_MASK;  a0 = fma2(wd, t, a0);  // j0
            t = add2(aA, BL.y) & ABS2_MASK;  a1 = fma2(wd, t, a1);  // j0+1
            t = add2(aA, BH.x) & ABS2_MASK;  a2 = fma2(wd, t, a2);  // j0+2
            t = add2(aA, BH.y) & ABS2_MASK;  a3 = fma2(wd, t, a3);  // j0+3
        }
    }

    // Epilogue: 2 rows x 4 cols per thread
    const int ig = ib + py * 2;
    const int jg = jb + tx * 4;
    const float4 cjv = *(const float4*)&g_cj[jg];
    const float  bb  = __ldg(b2);
    const float  ci0 = g_ci[ig];
    const float  ci1 = g_ci[ig + 1];

    float v00, v01, v10, v11, v20, v21, v30, v31;
    unpack2(a0, v00, v01);   // (j0, i) / (j0, i+1)
    unpack2(a1, v10, v11);
    unpack2(a2, v20, v21);
    unpack2(a3, v30, v31);

    float4 o0, o1;
    const float b0 = ci0 + bb, b1v = ci1 + bb;
    o0.x = v00 + cjv.x + b0;  o0.y = v10 + cjv.y + b0;
    o0.z = v20 + cjv.z + b0;  o0.w = v30 + cjv.w + b0;
    o1.x = v01 + cjv.x + b1v; o1.y = v11 + cjv.y + b1v;
    o1.z = v21 + cjv.z + b1v; o1.w = v31 + cjv.w + b1v;

    *(float4*)&out[ig * NN + jg]       = o0;
    *(float4*)&out[(ig + 1) * NN + jg] = o1;
}

// ---------------------------------------------------------------------------
// metadata order: z [1024*128], W1 [256*128], b1 [128], W2 [128], b2 [1]
// output: float32 [1024*1024]
// ---------------------------------------------------------------------------
extern "C" void kernel_launch(void* const* d_in, const int* in_sizes, int n_in,
                              void* d_out, int out_size)
{
    const float* z  = (const float*)d_in[0];
    const float* W1 = (const float*)d_in[1];
    const float* b1 = (const float*)d_in[2];
    const float* W2 = (const float*)d_in[3];
    const float* b2 = (const float*)d_in[4];
    float* out = (float*)d_out;

    prep_kernel<<<NN / 8, 512>>>(z, W1, b1, W2);
    cicj_kernel<<<256, 256>>>();

    dim3 grd(NN / 64, NN / 64);
    pair_kernel<<<grd, 512>>>(b2, out);
}

// round 9
// speedup vs baseline: 1.3032x; 1.3032x over previous
#include <cuda_runtime.h>

#define NN 1024
#define DD 128
#define DH 64    // d-range per z-slice of pair_kernel

// ---------------------------------------------------------------------------
// Device scratch (allocation-free)
// ---------------------------------------------------------------------------
__device__ float g_PIB [NN * DD];   // pi + b1, row-major (for ci)
__device__ float g_PIBT[DD * NN];   // pi + b1, transposed [d][i]
__device__ float g_PJ  [NN * DD];   // pj, row-major (for cj)
__device__ float g_PJT [DD * NN];   // pj, transposed [d][j]
__device__ float g_W2H [DD];        // 0.5 * W2
__device__ float g_ci  [NN];
__device__ float g_cj  [NN];
__device__ float g_P1  [NN * NN];   // partial sums for d in [64,128)

// ---------------------------------------------------------------------------
// f32x2 packed helpers (sm_103a)
// ---------------------------------------------------------------------------
__device__ __forceinline__ unsigned long long pack2(float lo, float hi) {
    unsigned long long r;
    asm("mov.b64 %0, {%1, %2};" : "=l"(r) : "f"(lo), "f"(hi));
    return r;
}
__device__ __forceinline__ void unpack2(unsigned long long v, float& lo, float& hi) {
    asm("mov.b64 {%0, %1}, %2;" : "=f"(lo), "=f"(hi) : "l"(v));
}
__device__ __forceinline__ unsigned long long add2(unsigned long long a, unsigned long long b) {
    unsigned long long r;
    asm("add.rn.f32x2 %0, %1, %2;" : "=l"(r) : "l"(a), "l"(b));
    return r;
}
__device__ __forceinline__ unsigned long long fma2(unsigned long long a, unsigned long long b,
                                                   unsigned long long c) {
    unsigned long long r;
    asm("fma.rn.f32x2 %0, %1, %2, %3;" : "=l"(r) : "l"(a), "l"(b), "l"(c));
    return r;
}
#define ABS2_MASK 0x7FFFFFFF7FFFFFFFULL

// ---------------------------------------------------------------------------
// Kernel A: prep (proven v3 structure; minblocks=1 to unlock registers so
// ptxas can front-batch the 16 unrolled W1 loads -> real MLP).
// 128 blocks x 512 threads. dc = tid&255 (concat column), h = tid>>8,
// 4 rows each, scalar W1 loads unroll 16.
// ---------------------------------------------------------------------------
__global__ void __launch_bounds__(512, 1) prep_kernel(
    const float* __restrict__ z, const float* __restrict__ W1,
    const float* __restrict__ b1, const float* __restrict__ W2)
{
    __shared__ float zs[8][DD];
    const int tid = threadIdx.x;         // 0..511
    const int dc  = tid & 255;           // concat output column
    const int h   = tid >> 8;            // row half (0/1) -> rows 4h..4h+3
    const int i0  = blockIdx.x * 8;

    if (blockIdx.x == 0 && tid < DD) g_W2H[tid] = 0.5f * W2[tid];

    if (tid < 256)
        ((float4*)zs)[tid] = ((const float4*)(z + i0 * DD))[tid];
    __syncthreads();

    const bool is_pi = (dc < DD);
    const int  d     = is_pi ? dc : dc - DD;
    const float* wcol = is_pi ? (W1 + d) : (W1 + DD * DD + d);
    const int r0 = 4 * h;

    float acc[4] = {0.f, 0.f, 0.f, 0.f};

    #pragma unroll 16
    for (int k = 0; k < DD; k++) {
        const float w = __ldg(&wcol[k * DD]);
        #pragma unroll
        for (int ii = 0; ii < 4; ii++)
            acc[ii] = fmaf(zs[r0 + ii][k], w, acc[ii]);
    }

    if (is_pi) {
        const float bb = __ldg(&b1[d]);
        #pragma unroll
        for (int ii = 0; ii < 4; ii++) acc[ii] += bb;
        #pragma unroll
        for (int ii = 0; ii < 4; ii++)
            g_PIB[(i0 + r0 + ii) * DD + d] = acc[ii];     // coalesced across dc
        *(float4*)&g_PIBT[d * NN + i0 + r0] = *(float4*)&acc[0];
    } else {
        #pragma unroll
        for (int ii = 0; ii < 4; ii++)
            g_PJ[(i0 + r0 + ii) * DD + d] = acc[ii];
        *(float4*)&g_PJT[d * NN + i0 + r0] = *(float4*)&acc[0];
    }
}

// ---------------------------------------------------------------------------
// Kernel B: ci[i] = g_PIB[i,:] . g_W2H ; cj[j] = g_PJ[j,:] . g_W2H
// ---------------------------------------------------------------------------
__global__ void __launch_bounds__(256) cicj_kernel()
{
    const int warp = blockIdx.x * 8 + (threadIdx.x >> 5);
    const int lane = threadIdx.x & 31;
    const bool is_ci = warp < NN;
    const int  row   = is_ci ? warp : warp - NN;
    const float* src = is_ci ? (g_PIB + row * DD) : (g_PJ + row * DD);

    float4 v = *(const float4*)(src + lane * 4);
    float4 w = *(const float4*)(g_W2H + lane * 4);
    float s = v.x * w.x + v.y * w.y + v.z * w.z + v.w * w.w;
    #pragma unroll
    for (int off = 16; off; off >>= 1)
        s += __shfl_down_sync(0xFFFFFFFFu, s, off);
    if (lane == 0) {
        if (is_ci) g_ci[row] = s; else g_cj[row] = s;
    }
}

// ---------------------------------------------------------------------------
// Kernel C (v3 = v1 inner loop + d-split): partial[i,j] over d-range of 64.
// Grid (16,16,2): z selects d in [z*64,(z+1)*64) and target (out / g_P1).
// 64i x 64j tile, 256 threads (16x16), 4i x 4j per thread, f32x2 packed.
// 512 blocks total -> ~28 warps/SM resident (vs 13.8 before).
// ---------------------------------------------------------------------------
#define TPAD 68   // row stride in floats (64 + 4), keeps 16B alignment

__global__ void __launch_bounds__(256, 4) pair_kernel(float* __restrict__ out)
{
    __shared__ float pisT[DH][TPAD];            // ~17.4 KB
    __shared__ float pjs [DH][TPAD];            // ~17.4 KB
    __shared__ unsigned long long w2p[DH];      //  512 B

    const int tx  = threadIdx.x;                // 0..15 -> 4 j
    const int ty  = threadIdx.y;                // 0..15 -> 4 i
    const int tid = ty * 16 + tx;
    const int ib  = blockIdx.y * 64;
    const int jb  = blockIdx.x * 64;
    const int db  = blockIdx.z * DH;            // d-range base

    // Stage tiles: [64 d][64] each, float4 coalesced, conflict-free STS
    for (int idx = tid; idx < DH * 16; idx += 256) {
        const int d = idx >> 4;
        const int q = idx & 15;
        *(float4*)&pisT[d][q * 4] =
            *(const float4*)&g_PIBT[(db + d) * NN + ib + q * 4];
        *(float4*)&pjs[d][q * 4] =
            *(const float4*)&g_PJT [(db + d) * NN + jb + q * 4];
    }
    if (tid < DH) {
        const float w = g_W2H[db + tid];
        w2p[tid] = pack2(w, w);
    }
    __syncthreads();

    const int i0 = ty * 4;                      // local i base
    const int j0 = tx * 4;                      // local j base

    unsigned long long acc[2][4];               // [i-pair][j]
    #pragma unroll
    for (int p = 0; p < 2; p++)
        #pragma unroll
        for (int j = 0; j < 4; j++) acc[p][j] = 0ULL;

    #pragma unroll 4
    for (int d = 0; d < DH; d++) {
        const ulonglong2 aA = *(const ulonglong2*)&pisT[d][i0];
        const float4 bf = *(const float4*)&pjs[d][j0];
        const unsigned long long bp[4] = {
            pack2(bf.x, bf.x), pack2(bf.y, bf.y),
            pack2(bf.z, bf.z), pack2(bf.w, bf.w) };
        const unsigned long long wd = w2p[d];

        #pragma unroll
        for (int j = 0; j < 4; j++) {
            unsigned long long t0 = add2(aA.x, bp[j]) & ABS2_MASK;
            acc[0][j] = fma2(wd, t0, acc[0][j]);
            unsigned long long t1 = add2(aA.y, bp[j]) & ABS2_MASK;
            acc[1][j] = fma2(wd, t1, acc[1][j]);
        }
    }

    // Write raw partials (rank-1 terms + b2 added in combine)
    float* dst = (blockIdx.z == 0) ? out : g_P1;

    float v[4][4];
    #pragma unroll
    for (int p = 0; p < 2; p++)
        #pragma unroll
        for (int j = 0; j < 4; j++) {
            float lo, hi;
            unpack2(acc[p][j], lo, hi);
            v[2 * p][j]     = lo;
            v[2 * p + 1][j] = hi;
        }

    #pragma unroll
    for (int r = 0; r < 4; r++) {
        float4 o;
        o.x = v[r][0]; o.y = v[r][1]; o.z = v[r][2]; o.w = v[r][3];
        *(float4*)&dst[(ib + i0 + r) * NN + jb + j0] = o;
    }
}

// ---------------------------------------------------------------------------
// Kernel D: out = out + g_P1 + ci[i] + cj[j] + b2   (1024 blocks x 256 thr)
// ---------------------------------------------------------------------------
__global__ void __launch_bounds__(256) combine_kernel(
    const float* __restrict__ b2, float* __restrict__ out)
{
    const int idx = (blockIdx.x * 256 + threadIdx.x) * 4;
    const int i = idx >> 10;
    const int j = idx & (NN - 1);

    float4 a  = *(float4*)&out[idx];
    const float4 p  = *(const float4*)&g_P1[idx];
    const float4 cj = *(const float4*)&g_cj[j];
    const float base = g_ci[i] + __ldg(b2);

    a.x += p.x + cj.x + base;
    a.y += p.y + cj.y + base;
    a.z += p.z + cj.z + base;
    a.w += p.w + cj.w + base;
    *(float4*)&out[idx] = a;
}

// ---------------------------------------------------------------------------
// metadata order: z [1024*128], W1 [256*128], b1 [128], W2 [128], b2 [1]
// output: float32 [1024*1024]
// ---------------------------------------------------------------------------
extern "C" void kernel_launch(void* const* d_in, const int* in_sizes, int n_in,
                              void* d_out, int out_size)
{
    const float* z  = (const float*)d_in[0];
    const float* W1 = (const float*)d_in[1];
    const float* b1 = (const float*)d_in[2];
    const float* W2 = (const float*)d_in[3];
    const float* b2 = (const float*)d_in[4];
    float* out = (float*)d_out;

    prep_kernel<<<NN / 8, 512>>>(z, W1, b1, W2);
    cicj_kernel<<<256, 256>>>();

    dim3 blk(16, 16);
    dim3 grd(NN / 64, NN / 64, 2);
    pair_kernel<<<grd, blk>>>(out);

    combine_kernel<<<NN * NN / (256 * 4), 256>>>(b2, out);
}